// round 6
// baseline (speedup 1.0000x reference)
#include <cuda_runtime.h>
#include <cstdint>
#include <math.h>

#define B_    64
#define C_    256
#define T_    1024
#define H_    512
#define S_TOT 192
#define S_RX0 64
#define BETA  0.9f
#define THR   0.75f

// ---- output layout (flattened tuple, float32) ----
#define OUT_D  0
#define OUT_A  (B_*H_)
#define OUT_E  (2*B_*H_)
#define OUT_RX (3*B_*H_)
#define OUT_PX (3*B_*H_ + B_*2*C_*T_)

// ---- static device scratch ----
__device__ float        g_acc   [(size_t)S_TOT * T_ * C_];  // mixed (pre-bias) [s][t][c]
__device__ unsigned int g_trace [128 * C_ * 32];            // rx spike bits [rb][c][t/32]
__device__ int          g_spkcnt[S_TOT * C_];
__device__ float        g_feat  [3 * B_ * C_];
// W digit planes in imma B-fragment order: [img 2][digit 4][q 8][j 32][lane 32][reg 2]
__device__ uint32_t     g_Bfrag [2 * 4 * 16384];

// ======================= helpers =========================
__device__ __forceinline__ uint32_t smem_to_u32(const void* p) {
    uint32_t a;
    asm("{ .reg .u64 t; cvta.to.shared.u64 t, %1; cvt.u32.u64 %0, t; }" : "=r"(a) : "l"(p));
    return a;
}

#define LDMATRIX_X4(r0, r1, r2, r3, addr) \
    asm volatile("ldmatrix.sync.aligned.m8n8.x4.shared.b16 {%0,%1,%2,%3}, [%4];" \
        : "=r"(r0), "=r"(r1), "=r"(r2), "=r"(r3) : "r"(addr))

// D = A(s8) * B(s8) + C, s32 accumulate, m16n8k32
#define IMMA(d, a, b0, b1, c) \
    asm volatile("mma.sync.aligned.m16n8k32.row.col.s32.s8.s8.s32 " \
        "{%0,%1,%2,%3}, {%4,%5,%6,%7}, {%8,%9}, {%10,%11,%12,%13};" \
        : "=r"((d)[0]), "=r"((d)[1]), "=r"((d)[2]), "=r"((d)[3]) \
        : "r"((a)[0]), "r"((a)[1]), "r"((a)[2]), "r"((a)[3]), \
          "r"(b0), "r"(b1), \
          "r"((c)[0]), "r"((c)[1]), "r"((c)[2]), "r"((c)[3]))

// ============================================================================
// K0w: quantize W to q=rint(w*2^30), split into 4 balanced signed bytes
// (exact: q = d0*2^24 + d1*2^16 + d2*2^8 + d3), packed in imma B-fragment
// order. v decode: reg=v&1, lane=(v>>1)&31, j=(v>>6)&31, q=v>>11;
// n = j*8 + (lane>>2); k = q*32 + reg*16 + (lane&3)*4 + byte.
// grid dim3(2, 64) x 256 threads.
// ============================================================================
__global__ void k0w(const float* __restrict__ W_tx, const float* __restrict__ W_rx)
{
    const int img = blockIdx.x;                 // 0=tx, 1=rx
    const float* W = img ? W_rx : W_tx;
    const int v = blockIdx.y * 256 + threadIdx.x;   // 0..16383

    const int reg = v & 1, lane = (v >> 1) & 31, j = (v >> 6) & 31, q = v >> 11;
    const int n  = j * 8 + (lane >> 2);
    const int k0 = q * 32 + reg * 16 + (lane & 3) * 4;

    uint32_t out[4] = {0u, 0u, 0u, 0u};
    #pragma unroll
    for (int e = 0; e < 4; e++) {
        const float w = W[n * 256 + k0 + e];
        int qw = __float2int_rn(w * 1073741824.0f);   // w * 2^30 (exact scale)
        const int d3 = (int)(signed char)(qw & 0xff); qw = (qw - d3) >> 8;
        const int d2 = (int)(signed char)(qw & 0xff); qw = (qw - d2) >> 8;
        const int d1 = (int)(signed char)(qw & 0xff); qw = (qw - d1) >> 8;
        const int d0 = qw;                             // |d0| <= ~68, fits s8
        out[0] |= ((uint32_t)(d0 & 0xff)) << (8 * e);
        out[1] |= ((uint32_t)(d1 & 0xff)) << (8 * e);
        out[2] |= ((uint32_t)(d2 & 0xff)) << (8 * e);
        out[3] |= ((uint32_t)(d3 & 0xff)) << (8 * e);
    }
    #pragma unroll
    for (int d = 0; d < 4; d++)
        g_Bfrag[(img * 4 + d) * 16384 + v] = out[d];
}

// ============================================================================
// K_GEMM: g_acc[s][t0..+127][nbase..+127] = spikes @ W^T, EXACT via int8
// 4-digit imma + exact int32 digit-pair accumulators + single final rounding.
// grid 3072 CTAs (s x 8 tblocks x 2 n-halves), 512 threads (16 warps 4x4,
// warp tile 32x32). smem: A 128x272B (pad row, no swizzle) + 4 B planes 128KB.
// ============================================================================
#define SM_A_BYTES 34816            // 128 * 272
#define SM_TOTAL   (SM_A_BYTES + 131072)

__global__ void __launch_bounds__(512, 1) k_gemm(const float* __restrict__ tx,
                                                 const float* __restrict__ rxsp)
{
    extern __shared__ unsigned char sm[];
    const uint32_t a_base = smem_to_u32(sm);

    const int tid = threadIdx.x, wid = tid >> 5, lane = tid & 31;
    const int wm = wid >> 2, wn = wid & 3;

    const int bx = blockIdx.x;
    const int s  = bx >> 4;
    const int tb = (bx >> 1) & 7;
    const int nh = bx & 1;
    const int t0 = tb * 128;
    const int nbase = nh * 128;
    const int jbase = nh * 16;

    const float* src = (s < S_RX0) ? tx + (size_t)s * C_ * T_
                                   : rxsp + (size_t)(s - S_RX0) * C_ * T_;
    const uint32_t* Bimg = g_Bfrag + ((s < S_RX0) ? 0 : 4 * 16384);

    // ---- phase 1: gmem -> byte staging [c 256][tq 32] u32 (4 t's per u32),
    // stride 33 u32 per channel row (bank-spread). Staging lives in B region.
    uint32_t* stg = (uint32_t*)(sm + SM_A_BYTES);
    #pragma unroll
    for (int i = 0; i < 16; i++) {
        const int task = tid + i * 512;           // 0..8191
        const int c = task >> 5, tq = task & 31;
        const float4 f = *(const float4*)(src + (size_t)c * T_ + t0 + tq * 4);
        const uint32_t p = (f.x > 0.5f ? 0x1u : 0u) | (f.y > 0.5f ? 0x100u : 0u)
                         | (f.z > 0.5f ? 0x10000u : 0u) | (f.w > 0.5f ? 0x1000000u : 0u);
        stg[c * 33 + tq] = p;
    }
    __syncthreads();

    // ---- phase 2: staging -> A tile int8 [t 128][k=c 256], row stride 272B.
    #pragma unroll
    for (int i = 0; i < 4; i++) {
        const int task = tid + i * 512;           // 0..2047
        const int t = task & 127, u = task >> 7;  // u = 16-byte unit 0..15
        const int tq = t >> 2, sel = (t & 3) * 8;
        uint32_t o[4];
        #pragma unroll
        for (int k4 = 0; k4 < 4; k4++) {
            const uint32_t b0 = stg[(u * 16 + k4 * 4 + 0) * 33 + tq] >> sel;
            const uint32_t b1 = stg[(u * 16 + k4 * 4 + 1) * 33 + tq] >> sel;
            const uint32_t b2 = stg[(u * 16 + k4 * 4 + 2) * 33 + tq] >> sel;
            const uint32_t b3 = stg[(u * 16 + k4 * 4 + 3) * 33 + tq] >> sel;
            o[k4] = (b0 & 0xffu) | ((b1 & 0xffu) << 8) | ((b2 & 0xffu) << 16) | ((b3 & 0xffu) << 24);
        }
        *(uint4*)(sm + t * 272 + u * 16) = make_uint4(o[0], o[1], o[2], o[3]);
    }
    __syncthreads();

    // ---- copy 4 digit B planes (n-half) into smem (overwrites staging)
    {
        const uint4* src4 = (const uint4*)Bimg;
        uint4* dst4 = (uint4*)(sm + SM_A_BYTES);
        #pragma unroll
        for (int i = tid; i < 8192; i += 512) {
            const int d = i >> 11, q = (i >> 8) & 7, jrem = i & 255;
            dst4[i] = src4[(d * 8 + q) * 512 + jbase * 16 + jrem];
        }
    }
    __syncthreads();

    const uint32_t* smB = (const uint32_t*)(sm + SM_A_BYTES);

    int accA[2][4][4], accB[2][4][4];
    #pragma unroll
    for (int mt = 0; mt < 2; mt++)
        #pragma unroll
        for (int nt = 0; nt < 4; nt++)
            #pragma unroll
            for (int e = 0; e < 4; e++) { accA[mt][nt][e] = 0; accB[mt][nt][e] = 0; }

    const int arow = wm * 32 + (lane & 15);

    #pragma unroll 1
    for (int q = 0; q < 8; q++) {
        uint32_t af[2][4];
        const int chunk = 2 * q + (lane >> 4);
        #pragma unroll
        for (int mt = 0; mt < 2; mt++) {
            const uint32_t addr = a_base + (arow + mt * 16) * 272 + (chunk << 4);
            LDMATRIX_X4(af[mt][0], af[mt][1], af[mt][2], af[mt][3], addr);
        }
        #pragma unroll
        for (int nt = 0; nt < 4; nt++) {
            const int off = ((q * 16 + wn * 4 + nt) * 32 + lane) * 2;
            const uint2 b0 = *(const uint2*)(smB + off);
            const uint2 b1 = *(const uint2*)(smB + 8192 + off);
            const uint2 b2 = *(const uint2*)(smB + 16384 + off);
            const uint2 b3 = *(const uint2*)(smB + 24576 + off);
            #pragma unroll
            for (int mt = 0; mt < 2; mt++) {
                int R[4] = {0, 0, 0, 0};
                IMMA(R, af[mt], b0.x, b0.y, R);
                int tq4[4];
                #pragma unroll
                for (int e = 0; e < 4; e++) tq4[e] = accA[mt][nt][e] + (R[e] << 8);
                IMMA(accA[mt][nt], af[mt], b1.x, b1.y, tq4);

                int R2[4] = {0, 0, 0, 0};
                IMMA(R2, af[mt], b2.x, b2.y, R2);
                #pragma unroll
                for (int e = 0; e < 4; e++) tq4[e] = accB[mt][nt][e] + (R2[e] << 8);
                IMMA(accB[mt][nt], af[mt], b3.x, b3.y, tq4);
            }
        }
    }

    // ---- epilogue: val = accA*2^-14 + accB*2^-30, single RNE rounding (fmaf)
    const int g = lane >> 2;
    #pragma unroll
    for (int mt = 0; mt < 2; mt++) {
        const int row = t0 + wm * 32 + mt * 16 + g;
        float* prow = g_acc + ((size_t)s * T_ + row) * C_;
        #pragma unroll
        for (int nt = 0; nt < 4; nt++) {
            const int col = nbase + wn * 32 + nt * 8 + (lane & 3) * 2;
            const float v0 = fmaf((float)accB[mt][nt][0], 0x1p-30f, (float)accA[mt][nt][0] * 0x1p-14f);
            const float v1 = fmaf((float)accB[mt][nt][1], 0x1p-30f, (float)accA[mt][nt][1] * 0x1p-14f);
            const float v2 = fmaf((float)accB[mt][nt][2], 0x1p-30f, (float)accA[mt][nt][2] * 0x1p-14f);
            const float v3 = fmaf((float)accB[mt][nt][3], 0x1p-30f, (float)accA[mt][nt][3] * 0x1p-14f);
            *(float2*)(prow + col)          = make_float2(v0, v1);
            *(float2*)(prow + 8 * C_ + col) = make_float2(v2, v3);
        }
    }
}

// ============================================================================
// K2b: LIF recurrence only. Thread per (s,c), 1024 steps, loads batched x32.
// (source identical to R3-passing version)
// ============================================================================
__global__ void k2b_scan(const float* __restrict__ b_tx, const float* __restrict__ b_rx)
{
    const int gid = blockIdx.x * 128 + threadIdx.x;   // 0..49151
    const int s = gid >> 8, c = gid & 255;
    const bool is_rx = (s >= S_RX0);
    const float bias = is_rx ? b_rx[c] : b_tx[c];
    const float* ap = g_acc + (size_t)s * T_ * C_ + c;
    const unsigned tb = is_rx ? ((unsigned)(s - S_RX0) * C_ + c) * 32u : 0u;

    float m = 0.0f, sub = 0.0f;
    int cnt = 0;

    #pragma unroll 1
    for (int t32 = 0; t32 < 32; ++t32) {
        float av[32];
        #pragma unroll
        for (int k = 0; k < 32; ++k)
            av[k] = ap[(size_t)(t32 * 32 + k) * C_];
        unsigned word = 0;
        #pragma unroll
        for (int k = 0; k < 32; ++k) {
            m = BETA * m + (av[k] + bias) - sub;
            const bool sp = m > THR;
            sub = sp ? THR : 0.0f;
            word |= (sp ? 1u : 0u) << k;
        }
        if (is_rx) g_trace[tb + t32] = word;
        cnt += __popc(word);
    }
    g_spkcnt[s * C_ + c] = cnt;
}

// ============================================================================
// K3: expand rx spike bits -> float32 trace in d_out (coalesced LUT expansion)
// ============================================================================
__global__ void k3_expand(float* __restrict__ out)
{
    __shared__ float4 lut[16];
    if (threadIdx.x < 16)
        lut[threadIdx.x] = make_float4((float)(threadIdx.x & 1), (float)((threadIdx.x >> 1) & 1),
                                       (float)((threadIdx.x >> 2) & 1), (float)((threadIdx.x >> 3) & 1));
    __syncthreads();

    const int row = blockIdx.x * 8 + (threadIdx.x >> 5);   // 0..32767
    const int l   = threadIdx.x & 31;
    const unsigned word = g_trace[(size_t)row * 32 + l];
    float4* dst = (float4*)(out + OUT_RX + (size_t)row * T_);
    #pragma unroll
    for (int k = 0; k < 8; k++) {
        const int t4   = k * 32 + l;
        const unsigned wsrc = __shfl_sync(0xffffffffu, word, t4 >> 3);
        const unsigned nib  = (wsrc >> ((t4 & 7) * 4)) & 0xFu;
        dst[t4] = lut[nib];
    }
}

// ============================================================================
// K4a: features + layernorm + spike_proxy
// ============================================================================
__device__ __forceinline__ float blk_sum(float v, float* red, int c)
{
    red[c] = v; __syncthreads();
    #pragma unroll
    for (int off = 128; off > 0; off >>= 1) {
        if (c < off) red[c] += red[c + off];
        __syncthreads();
    }
    float s = red[0]; __syncthreads();
    return s;
}

__global__ void k4a_feat(float* __restrict__ out)
{
    __shared__ float red[256];
    const int b = blockIdx.x, c = threadIdx.x;
    const int cd = g_spkcnt[b * C_ + c];
    const int cl = g_spkcnt[(S_RX0 + b * 2 + 0) * C_ + c];
    const int cr = g_spkcnt[(S_RX0 + b * 2 + 1) * C_ + c];

    out[OUT_PX + (size_t)(b * 2 + 0) * C_ + c] = (float)cl;
    out[OUT_PX + (size_t)(b * 2 + 1) * C_ + c] = (float)cr;

    float f[3];
    f[0] = (float)cd        * (1.0f / 1024.0f);
    f[1] = (float)(cl - cr) * (1.0f / 1024.0f);
    f[2] = (float)(cl + cr) * (1.0f / 1024.0f);

    #pragma unroll
    for (int typ = 0; typ < 3; typ++) {
        const float mu = blk_sum(f[typ], red, c) * (1.0f / 256.0f);
        const float xc = f[typ] - mu;
        const float var = blk_sum(xc * xc, red, c) * (1.0f / 256.0f);
        g_feat[(typ * B_ + b) * C_ + c] = xc / sqrtf(var + 1e-5f);
    }
}

// ============================================================================
// K4b: heads — [64x256]@[256x512]^T + bias, gain, residual, relu.
// ============================================================================
__global__ void k4b_head(const float* __restrict__ Wd, const float* __restrict__ bd,
                         const float* __restrict__ Wa, const float* __restrict__ ba,
                         const float* __restrict__ We, const float* __restrict__ be,
                         const float* __restrict__ base_d, const float* __restrict__ base_a,
                         const float* __restrict__ base_e,
                         const float* __restrict__ gd, const float* __restrict__ ga,
                         const float* __restrict__ ge,
                         float* __restrict__ out)
{
    extern __shared__ float x_sh[];   // 64*256 floats
    const int typ = blockIdx.x >> 6;
    const int h0  = (blockIdx.x & 63) * 8;

    const float* feat = g_feat + (size_t)typ * B_ * C_;
    for (int i = threadIdx.x; i < B_ * C_; i += 256) x_sh[i] = feat[i];
    __syncthreads();

    const float* Wm   = (typ == 0) ? Wd : (typ == 1) ? Wa : We;
    const float* bm   = (typ == 0) ? bd : (typ == 1) ? ba : be;
    const float* bsp  = (typ == 0) ? base_d : (typ == 1) ? base_a : base_e;
    const float  g    = (typ == 0) ? *gd : (typ == 1) ? *ga : *ge;
    const float  sg   = 0.3f / (1.0f + expf(-g));
    const size_t ooff = (typ == 0) ? OUT_D : (typ == 1) ? OUT_A : OUT_E;

    const int lane = threadIdx.x & 31;
    const int h    = h0 + (threadIdx.x >> 5);

    const float4* wrow = (const float4*)(Wm + (size_t)h * C_);
    const float4 w0 = wrow[lane * 2];
    const float4 w1 = wrow[lane * 2 + 1];
    const float  bh = bm[h];

    for (int b = 0; b < B_; b++) {
        const float4* xb = (const float4*)(x_sh + b * C_ + lane * 8);
        const float4 x0 = xb[0], x1 = xb[1];
        float p = w0.x * x0.x + w0.y * x0.y + w0.z * x0.z + w0.w * x0.w
                + w1.x * x1.x + w1.y * x1.y + w1.z * x1.z + w1.w * x1.w;
        #pragma unroll
        for (int off = 16; off > 0; off >>= 1)
            p += __shfl_xor_sync(0xffffffffu, p, off);
        if (lane == 0) {
            const float r = p + bh;
            const float v = bsp[(size_t)b * H_ + h] + sg * r;
            out[ooff + (size_t)b * H_ + h] = v > 0.0f ? v : 0.0f;
        }
    }
}

// ============================================================================
extern "C" void kernel_launch(void* const* d_in, const int* in_sizes, int n_in,
                              void* d_out, int out_size)
{
    const float* tx    = (const float*)d_in[0];
    const float* rxsp  = (const float*)d_in[1];
    const float* bsd   = (const float*)d_in[2];
    const float* bsa   = (const float*)d_in[3];
    const float* bse   = (const float*)d_in[4];
    const float* W_tx  = (const float*)d_in[5];
    const float* b_tx  = (const float*)d_in[6];
    const float* W_rx  = (const float*)d_in[7];
    const float* b_rx  = (const float*)d_in[8];
    const float* Wd    = (const float*)d_in[9];
    const float* bd    = (const float*)d_in[10];
    const float* Wa    = (const float*)d_in[11];
    const float* ba    = (const float*)d_in[12];
    const float* We    = (const float*)d_in[13];
    const float* be    = (const float*)d_in[14];
    const float* gd    = (const float*)d_in[15];
    const float* ga    = (const float*)d_in[16];
    const float* ge    = (const float*)d_in[17];
    float* out = (float*)d_out;

    static bool attr_set = false;
    if (!attr_set) {
        cudaFuncSetAttribute(k_gemm, cudaFuncAttributeMaxDynamicSharedMemorySize, SM_TOTAL);
        cudaFuncSetAttribute(k4b_head, cudaFuncAttributeMaxDynamicSharedMemorySize, 65536);
        attr_set = true;
    }

    k0w<<<dim3(2, 64), 256>>>(W_tx, W_rx);
    k_gemm<<<S_TOT * 16, 512, SM_TOTAL>>>(tx, rxsp);
    k2b_scan<<<384, 128>>>(b_tx, b_rx);
    k3_expand<<<4096, 256>>>(out);
    k4a_feat<<<B_, 256>>>(out);
    k4b_head<<<3 * 64, 256, 65536>>>(Wd, bd, Wa, ba, We, be, bsd, bsa, bse, gd, ga, ge, out);
}